// round 12
// baseline (speedup 1.0000x reference)
#include <cuda_runtime.h>
#include <cuda_bf16.h>
#include <cfloat>

#define NN 2048
#define FF 64
#define KTOP 8
#define OUT_ROW ((KTOP + 1) * FF)   // 576

#define NBINS 512
#define BIN_HI 4.25f
#define BIN_W  (8.5f / (float)NBINS)
#define BIN_INVW ((float)NBINS / 8.5f)

#define SSTAGE 512
#define BATCH 8

__device__ float g_sink;   // never actually written (adj >= 0)

__device__ __forceinline__ int bin_of(float v) {
    int b = (int)((BIN_HI - v) * BIN_INVW);
    return max(0, min(NBINS - 1, b));
}
__device__ __forceinline__ float remaining_bound(float v) {
    int b = bin_of(v);
    return (b == 0) ? FLT_MAX : (BIN_HI - (float)b * BIN_W + 1e-3f);
}

// ---------------------------------------------------------------------------
// Single fused kernel: adj L2 prewarm + per-block feature binning (to smem)
// + pruned top-8 scan with depth-4 rotating prefetch.
// One warp per (f, 32 consecutive m); 128-thread blocks share f; grid 1024.
// ---------------------------------------------------------------------------
__global__ void __launch_bounds__(128, 8) fused_topk_kernel(
        const float* __restrict__ adj,
        const float* __restrict__ x,
        float* __restrict__ out) {
    __shared__ float sx  [NN];       // 8 KB: x column for feature f
    __shared__ float sxv [SSTAGE];   // 2 KB: candidate x values (binned order)
    __shared__ int   soff[SSTAGE];   // 2 KB: candidate adj row offsets (n*NN)
    __shared__ float sbd [SSTAGE];   // 2 KB: bound on all later products
    __shared__ int   cnt [NBINS];    // 2 KB
    __shared__ int   sa  [NBINS];    // 2 KB
    __shared__ int   sb  [NBINS];    // 2 KB
    __shared__ int   cur [NBINS];    // 2 KB

    const int tid  = threadIdx.x;
    const int f    = blockIdx.x >> 4;                        // 16 blocks/feature
    const int mg   = (blockIdx.x & 15) * 4 + (tid >> 5);
    const int lane = tid & 31;
    const int m    = mg * 32 + lane;

    // --- adj L2 prewarm: each block streams its 16 KB contiguous slice ---
    // (spread across 1024 blocks => LSU-cheap; DRAM latency overlaps binning)
    float acc = 0.0f;
    {
        const float4* aw = (const float4*)adj + (size_t)blockIdx.x * 1024 + tid;
#pragma unroll
        for (int i = 0; i < 8; i++) {
            float4 w = __ldg(aw + i * 128);
            acc += w.x + w.y + w.z + w.w;
        }
    }

    // --- binning phase (per-block, feature f) ---
    for (int i = tid; i < NBINS; i += 128) cnt[i] = 0;
    __syncthreads();

    for (int i = tid; i < NN; i += 128) {
        float v = __ldg(&x[i * FF + f]);
        sx[i] = v;
        atomicAdd(&cnt[bin_of(v)], 1);
    }
    __syncthreads();

    // Hillis-Steele inclusive scan over 512 bins (128 threads, 4 elems each)
    for (int i = tid; i < NBINS; i += 128) sa[i] = cnt[i];
    __syncthreads();
    int* src = sa; int* dst = sb;
    for (int d = 1; d < NBINS; d <<= 1) {
        for (int i = tid; i < NBINS; i += 128)
            dst[i] = src[i] + ((i >= d) ? src[i - d] : 0);
        __syncthreads();
        int* t = src; src = dst; dst = t;
    }
    for (int i = tid; i < NBINS; i += 128) cur[i] = src[i] - cnt[i];  // exclusive
    __syncthreads();

    // Scatter the first SSTAGE candidates (descending-bin order) into smem
    for (int i = tid; i < NN; i += 128) {
        float v = sx[i];
        int b = bin_of(v);
        int pos = atomicAdd(&cur[b], 1);
        if (pos < SSTAGE) {
            sxv[pos]  = v;
            soff[pos] = i * NN;
            sbd[pos]  = fmaxf(remaining_bound(v), 0.0f);
        }
    }
    __syncthreads();

    // --- pruned top-8 scan (R10-proven loop) ---
    const float* __restrict__ acol = adj + m;

    float arr[KTOP];
#pragma unroll
    for (int j = 0; j < KTOP; j++) arr[j] = -FLT_MAX;

    float a0[BATCH], a1[BATCH], a2[BATCH], a3[BATCH];

#define PREF(AB, b) do {                                                    \
    _Pragma("unroll")                                                       \
    for (int c = 0; c < BATCH; c++)                                         \
        AB[c] = __ldg(acol + soff[(b) + c]);                                \
    } while (0)

// Batch vote; on pass, insert all 8 unconditionally (chain is a no-op for
// values below arr[7]).
#define PROC(AB, b) do {                                                    \
    float v[BATCH];                                                         \
    _Pragma("unroll")                                                       \
    for (int c = 0; c < BATCH; c++) v[c] = AB[c] * sxv[(b) + c];            \
    float m01 = fmaxf(v[0], v[1]), m23 = fmaxf(v[2], v[3]);                 \
    float m45 = fmaxf(v[4], v[5]), m67 = fmaxf(v[6], v[7]);                 \
    float vmax = fmaxf(fmaxf(m01, m23), fmaxf(m45, m67));                   \
    if (__any_sync(0xffffffffu, vmax > arr[KTOP - 1])) {                    \
        _Pragma("unroll")                                                   \
        for (int c = 0; c < BATCH; c++) {                                   \
            float keep = v[c];                                              \
            _Pragma("unroll")                                               \
            for (int j = 0; j < KTOP; j++) {                                \
                float mx = fmaxf(arr[j], keep);                             \
                keep     = fminf(arr[j], keep);                             \
                arr[j]   = mx;                                              \
            } } } } while (0)

#define TERM(b) (!__any_sync(0xffffffffu, sbd[(b) + BATCH - 1] > arr[KTOP - 1]))

    PREF(a0, 0); PREF(a1, BATCH); PREF(a2, 2 * BATCH); PREF(a3, 3 * BATCH);

    int base = 0;
    bool fin = false;

    // Steady state: 4 batches (32 loads) always in flight.
    while (base + 5 * BATCH <= SSTAGE) {
        PROC(a0, base); if (TERM(base)) { fin = true; break; }
        PREF(a0, base + 4 * BATCH); base += BATCH;
        PROC(a1, base); if (TERM(base)) { fin = true; break; }
        PREF(a1, base + 4 * BATCH); base += BATCH;
        PROC(a2, base); if (TERM(base)) { fin = true; break; }
        PREF(a2, base + 4 * BATCH); base += BATCH;
        PROC(a3, base); if (TERM(base)) { fin = true; break; }
        PREF(a3, base + 4 * BATCH); base += BATCH;
    }

    if (!fin) {   // drain: buffers hold base .. base+31 (exactly to SSTAGE)
        PROC(a0, base); fin = TERM(base); base += BATCH;
        if (!fin) { PROC(a1, base); fin = TERM(base); base += BATCH; }
        if (!fin) { PROC(a2, base); fin = TERM(base); base += BATCH; }
        if (!fin) { PROC(a3, base); fin = TERM(base); base += BATCH; }
    }

    // Brute-force fallback (probability ~0; preserves exactness).
    // Restart from scratch over ALL n using the x column in smem.
    if (!fin) {
#pragma unroll
        for (int j = 0; j < KTOP; j++) arr[j] = -FLT_MAX;
        for (int n = 0; n < NN; n += BATCH) {
#pragma unroll
            for (int c = 0; c < BATCH; c++)
                a0[c] = __ldg(acol + (size_t)(n + c) * NN);
#pragma unroll
            for (int c = 0; c < BATCH; c++) {
                float v = a0[c] * sx[n + c];
                if (__any_sync(0xffffffffu, v > arr[KTOP - 1])) {
                    float keep = v;
#pragma unroll
                    for (int j = 0; j < KTOP; j++) {
                        float mx = fmaxf(arr[j], keep);
                        keep     = fminf(arr[j], keep);
                        arr[j]   = mx;
                    }
                }
            }
        }
    }
#undef PREF
#undef PROC
#undef TERM

    // out[m, 1+j, f]
    float* o = out + (size_t)m * OUT_ROW + FF + f;
#pragma unroll
    for (int j = 0; j < KTOP; j++) o[j * FF] = arr[j];

    // k=0 slice: out[m, 0, f] = x[m, f]  (from smem column)
    out[(size_t)m * OUT_ROW + f] = sx[m];

    if (acc < -1.0f) g_sink = acc;   // never true (adj >= 0); keeps prewarm live
}

extern "C" void kernel_launch(void* const* d_in, const int* in_sizes, int n_in,
                              void* d_out, int out_size) {
    const float* x   = (const float*)d_in[0];
    const float* adj = (const float*)d_in[1];
    if (in_sizes[0] == NN * NN) {
        adj = (const float*)d_in[0];
        x   = (const float*)d_in[1];
    }
    float* out = (float*)d_out;

    // Single fused launch: 64 f * 16 blocks/f = 1024 blocks of 128 threads
    fused_topk_kernel<<<1024, 128>>>(adj, x, out);
}

// round 13
// speedup vs baseline: 1.2821x; 1.2821x over previous
#include <cuda_runtime.h>
#include <cuda_bf16.h>
#include <cfloat>

#define NN 2048
#define FF 64
#define KTOP 8
#define OUT_ROW ((KTOP + 1) * FF)   // 576

#define NBINS 512
#define BIN_HI 4.25f
#define BIN_W  (8.5f / (float)NBINS)
#define BIN_INVW ((float)NBINS / 8.5f)

#define SSTAGE 512
#define BATCH 8

// Per-feature candidate lists, descending value-bins (split arrays).
__device__ float g_xval[FF * NN];
__device__ int   g_off [FF * NN];
__device__ float g_bnd [FF * NN];
__device__ float g_sink;            // never actually written (adj >= 0)

__device__ __forceinline__ int bin_of(float v) {
    int b = (int)((BIN_HI - v) * BIN_INVW);
    return max(0, min(NBINS - 1, b));
}
__device__ __forceinline__ float remaining_bound(float v) {
    int b = bin_of(v);
    return (b == 0) ? FLT_MAX : (BIN_HI - (float)b * BIN_W + 1e-3f);
}

// ---------------------------------------------------------------------------
// Kernel 1: per-feature bucket binning, 4 blocks per feature.
// Block (f, q) loads the whole column, histograms per 512-row chunk,
// computes deterministic per-chunk bin offsets, scatters ONLY chunk q
// (one element per thread).
// ---------------------------------------------------------------------------
__global__ void __launch_bounds__(512) bin_cols_kernel(const float* __restrict__ x) {
    __shared__ float sx[NN];          // 8 KB: full column
    __shared__ int   cnt4[4][NBINS];  // 8 KB: per-chunk histograms
    __shared__ int   sa[NBINS];       // 2 KB
    __shared__ int   sb[NBINS];       // 2 KB
    __shared__ int   cur[NBINS];      // 2 KB: this chunk's cursors

    const int f   = blockIdx.x >> 2;
    const int q   = blockIdx.x & 3;
    const int tid = threadIdx.x;      // 512 threads

    // zero chunk histograms (4*512 ints / 512 threads = 4 each)
#pragma unroll
    for (int c = 0; c < 4; c++) cnt4[c][tid] = 0;
    __syncthreads();

    // Load full column with explicit ILP=4, then histogram per chunk.
    // Element i = c*512 + tid lies in chunk c.
    float v0 = __ldg(&x[(0 * 512 + tid) * FF + f]);
    float v1 = __ldg(&x[(1 * 512 + tid) * FF + f]);
    float v2 = __ldg(&x[(2 * 512 + tid) * FF + f]);
    float v3 = __ldg(&x[(3 * 512 + tid) * FF + f]);
    sx[0 * 512 + tid] = v0;
    sx[1 * 512 + tid] = v1;
    sx[2 * 512 + tid] = v2;
    sx[3 * 512 + tid] = v3;
    atomicAdd(&cnt4[0][bin_of(v0)], 1);
    atomicAdd(&cnt4[1][bin_of(v1)], 1);
    atomicAdd(&cnt4[2][bin_of(v2)], 1);
    atomicAdd(&cnt4[3][bin_of(v3)], 1);
    __syncthreads();

    // Total per-bin counts + inclusive scan (Hillis-Steele, 9 steps; 1 elem/thread)
    const int total = cnt4[0][tid] + cnt4[1][tid] + cnt4[2][tid] + cnt4[3][tid];
    sa[tid] = total;
    __syncthreads();
    int* src = sa; int* dst = sb;
    for (int d = 1; d < NBINS; d <<= 1) {
        dst[tid] = src[tid] + ((tid >= d) ? src[tid - d] : 0);
        __syncthreads();
        int* t = src; src = dst; dst = t;
    }
    // exclusive global base + offsets of chunks before q
    {
        int off = src[tid] - total;             // exclusive base for bin=tid
        for (int c = 0; c < q; c++) off += cnt4[c][tid];
        cur[tid] = off;
    }
    __syncthreads();

    // Scatter chunk q: one element per thread
    {
        const int i = q * 512 + tid;
        const float v = sx[i];
        const int b = bin_of(v);
        const int pos = atomicAdd(&cur[b], 1);
        float* oxv = g_xval + (size_t)f * NN;
        int*   oof = g_off  + (size_t)f * NN;
        float* obd = g_bnd  + (size_t)f * NN;
        oxv[pos] = v;
        oof[pos] = i * NN;
        obd[pos] = fmaxf(remaining_bound(v), 0.0f);
    }
}

// ---------------------------------------------------------------------------
// Kernel 2: pruned top-8 scan (R10 champion) + adj L2 prewarm.
// One warp per (f, 32 consecutive m); 128-thread blocks share f; grid 1024.
// Depth-4 rotating prefetch = 32 loads in flight per warp.
// PREF issued BEFORE the termination vote (loads not gated by the branch).
// ---------------------------------------------------------------------------
__global__ void __launch_bounds__(128, 8) topk_scan_kernel(
        const float* __restrict__ adj,
        const float* __restrict__ x,
        float* __restrict__ out) {
    __shared__ float sxv[SSTAGE];
    __shared__ int   soff[SSTAGE];
    __shared__ float sbd[SSTAGE];

    const int f    = blockIdx.x >> 4;                        // 16 blocks/feature
    const int mg   = (blockIdx.x & 15) * 4 + (threadIdx.x >> 5);
    const int lane = threadIdx.x & 31;
    const int m    = mg * 32 + lane;

    // --- adj L2 prewarm: each block streams its 16 KB contiguous slice ---
    {
        const float4* aw = (const float4*)adj
                         + (size_t)blockIdx.x * 1024 + threadIdx.x;
        float acc = 0.0f;
#pragma unroll
        for (int i = 0; i < 8; i++) {
            float4 w = __ldg(aw + i * 128);
            acc += w.x + w.y + w.z + w.w;
        }
        if (acc < -1.0f) g_sink = acc;   // never true (adj >= 0); keeps loads live
    }

    const float* __restrict__ gxv = g_xval + (size_t)f * NN;
    const int*   __restrict__ gof = g_off  + (size_t)f * NN;
    const float* __restrict__ gbd = g_bnd  + (size_t)f * NN;

    {
        const float4* s1 = (const float4*)gxv;
        const float4* s2 = (const float4*)gof;
        const float4* s3 = (const float4*)gbd;
        float4* d1 = (float4*)sxv;
        float4* d2 = (float4*)soff;
        float4* d3 = (float4*)sbd;
        for (int i = threadIdx.x; i < SSTAGE / 4; i += 128) {
            d1[i] = __ldg(s1 + i);
            d2[i] = __ldg(s2 + i);
            d3[i] = __ldg(s3 + i);
        }
    }
    __syncthreads();

    const float* __restrict__ acol = adj + m;

    float arr[KTOP];
#pragma unroll
    for (int j = 0; j < KTOP; j++) arr[j] = -FLT_MAX;

    float a0[BATCH], a1[BATCH], a2[BATCH], a3[BATCH];

#define PREF(AB, b) do {                                                    \
    _Pragma("unroll")                                                       \
    for (int c = 0; c < BATCH; c++)                                         \
        AB[c] = __ldg(acol + soff[(b) + c]);                                \
    } while (0)

// Batch vote; on pass, insert all 8 unconditionally (chain is a no-op for
// values below arr[7]).
#define PROC(AB, b) do {                                                    \
    float v[BATCH];                                                         \
    _Pragma("unroll")                                                       \
    for (int c = 0; c < BATCH; c++) v[c] = AB[c] * sxv[(b) + c];            \
    float m01 = fmaxf(v[0], v[1]), m23 = fmaxf(v[2], v[3]);                 \
    float m45 = fmaxf(v[4], v[5]), m67 = fmaxf(v[6], v[7]);                 \
    float vmax = fmaxf(fmaxf(m01, m23), fmaxf(m45, m67));                   \
    if (__any_sync(0xffffffffu, vmax > arr[KTOP - 1])) {                    \
        _Pragma("unroll")                                                   \
        for (int c = 0; c < BATCH; c++) {                                   \
            float keep = v[c];                                              \
            _Pragma("unroll")                                               \
            for (int j = 0; j < KTOP; j++) {                                \
                float mx = fmaxf(arr[j], keep);                             \
                keep     = fminf(arr[j], keep);                             \
                arr[j]   = mx;                                              \
            } } } } while (0)

#define TERM(b) (!__any_sync(0xffffffffu, sbd[(b) + BATCH - 1] > arr[KTOP - 1]))

    PREF(a0, 0); PREF(a1, BATCH); PREF(a2, 2 * BATCH); PREF(a3, 3 * BATCH);

    int base = 0;
    bool fin = false;

    // Steady state: 4 batches (32 loads) in flight; prefetch issued before
    // the termination vote so loads are not gated by the branch.
    while (base + 5 * BATCH <= SSTAGE) {
        PROC(a0, base); PREF(a0, base + 4 * BATCH);
        if (TERM(base)) { fin = true; break; }
        base += BATCH;
        PROC(a1, base); PREF(a1, base + 4 * BATCH);
        if (TERM(base)) { fin = true; break; }
        base += BATCH;
        PROC(a2, base); PREF(a2, base + 4 * BATCH);
        if (TERM(base)) { fin = true; break; }
        base += BATCH;
        PROC(a3, base); PREF(a3, base + 4 * BATCH);
        if (TERM(base)) { fin = true; break; }
        base += BATCH;
    }

    if (!fin) {   // drain: buffers hold base .. base+31 (exactly to SSTAGE)
        PROC(a0, base); fin = TERM(base); base += BATCH;
        if (!fin) { PROC(a1, base); fin = TERM(base); base += BATCH; }
        if (!fin) { PROC(a2, base); fin = TERM(base); base += BATCH; }
        if (!fin) { PROC(a3, base); fin = TERM(base); base += BATCH; }
    }

    // Global fallback (rarely reached; preserves exactness)
    while (!fin && base + BATCH <= NN) {
        float xg[BATCH];
#pragma unroll
        for (int c = 0; c < BATCH; c++) {
            a0[c] = __ldg(acol + __ldg(&gof[base + c]));
            xg[c] = __ldg(&gxv[base + c]);
        }
#pragma unroll
        for (int c = 0; c < BATCH; c++) {
            float v = a0[c] * xg[c];
            if (__any_sync(0xffffffffu, v > arr[KTOP - 1])) {
                float keep = v;
#pragma unroll
                for (int j = 0; j < KTOP; j++) {
                    float mx = fmaxf(arr[j], keep);
                    keep     = fminf(arr[j], keep);
                    arr[j]   = mx;
                }
            }
        }
        float bd = __ldg(&gbd[base + BATCH - 1]);
        if (!__any_sync(0xffffffffu, bd > arr[KTOP - 1])) fin = true;
        base += BATCH;
    }
#undef PREF
#undef PROC
#undef TERM

    // out[m, 1+j, f]
    float* o = out + (size_t)m * OUT_ROW + FF + f;
#pragma unroll
    for (int j = 0; j < KTOP; j++) o[j * FF] = arr[j];

    // k=0 slice: out[m, 0, f] = x[m, f]
    out[(size_t)m * OUT_ROW + f] = __ldg(&x[m * FF + f]);
}

extern "C" void kernel_launch(void* const* d_in, const int* in_sizes, int n_in,
                              void* d_out, int out_size) {
    const float* x   = (const float*)d_in[0];
    const float* adj = (const float*)d_in[1];
    if (in_sizes[0] == NN * NN) {
        adj = (const float*)d_in[0];
        x   = (const float*)d_in[1];
    }
    float* out = (float*)d_out;

    // 64 f * 4 chunks = 256 blocks of 512 threads
    bin_cols_kernel<<<256, 512>>>(x);

    // 64 f * 16 blocks/f = 1024 blocks of 128 threads (4 warps each)
    topk_scan_kernel<<<1024, 128>>>(adj, x, out);
}